// round 11
// baseline (speedup 1.0000x reference)
#include <cuda_runtime.h>
#include <cuda_bf16.h>
#include <cstdint>

// InterLayerTrajectoryFlow: fused diff -> normalize -> causal 6-tap weighted sum.
// emb: [B, S, D] fp32, S=8192, D=512.
//
// Persistent-strip cp.async pipeline: block = 256 threads owns 64 positions
// (8 iters x 8). Embedding rows stream through a 32-row smem ring (4 groups
// of 8 rows) via cp.async; groups t+2/t+3 load while iter t computes, so
// DRAM stays busy through the barrier phases. Rows (not diffs) are stored;
// the diff folds into telescoped 7-tap coefficients a_j. Norm weights come
// from constant tables (no expf).
//
// (R10 fix: missing <cstdint> — the R8/R9 failures were compile errors,
// not infra. Logic unchanged from the audited R7 design.)

#define S_LEN 8192
#define D_DIM 512
#define C4    128             // float4 groups per row
#define PI    8               // positions per iteration
#define STRIP 64              // positions per block
#define NIT   (STRIP / PI)    // 8 iterations
#define RING  32              // rows in ring (4 groups of 8)
#define NDIFF 13              // diff rows per iteration (recomputed)

#define RING_F    (RING * D_DIM)          // 16384 floats (64KB)
#define SPART_OFF RING_F                  // [13][16]
#define SRINV_OFF (SPART_OFF + NDIFF * 16)
#define SCA_OFF   (SRINV_OFF + 16)        // [8][7]
#define SMEM_F    (SCA_OFF + PI * 7 + 8)
#define SMEM_BYTES (SMEM_F * 4)

__constant__ float WT[36] = {
    0.36787944117f, 0.f, 0.f, 0.f, 0.f, 0.f,                                  // w=1
    1.0f, 0.36787944117f, 0.f, 0.f, 0.f, 0.f,                                 // w=2
    1.0f, 0.60653065971f, 0.36787944117f, 0.f, 0.f, 0.f,                      // w=3
    1.0f, 0.71653131057f, 0.51341711903f, 0.36787944117f, 0.f, 0.f,           // w=4
    1.0f, 0.77880078307f, 0.60653065971f, 0.47236655274f, 0.36787944117f, 0.f,// w=5
    1.0f, 0.81873075308f, 0.67032004604f, 0.54881163609f, 0.44932896412f, 0.36787944117f // w=6
};
__constant__ float WSUM[6] = {
    0.36787944117f, 1.36787944117f, 1.97441010088f,
    2.59782787077f, 3.22557744069f, 3.85507084050f
};

__device__ __forceinline__ void cp_async16(uint32_t dst, const void* src, bool valid) {
    int sz = valid ? 16 : 0;
    asm volatile("cp.async.cg.shared.global [%0], [%1], 16, %2;\n"
                 :: "r"(dst), "l"(src), "r"(sz));
}
__device__ __forceinline__ void cp_commit() {
    asm volatile("cp.async.commit_group;\n" ::: "memory");
}

__global__ __launch_bounds__(256, 3)
void traj_flow_kernel(const float* __restrict__ emb,
                      const int* __restrict__ layer_idx,
                      float* __restrict__ out) {
    extern __shared__ float sm[];
    const float4* ring4 = (const float4*)sm;

    const int tid   = threadIdx.x;
    const int c4    = tid & (C4 - 1);      // float4 column group 0..127
    const int phase = tid >> 7;            // 0..1
    const int lane  = tid & 31;
    const int wip   = (tid >> 5) & 3;      // warp within phase
    const int wid   = tid >> 5;            // warp 0..7
    const int b     = blockIdx.y;
    const int strip0 = blockIdx.x * STRIP; // first position of strip
    const int R0    = strip0 - 6;          // first ring row (absolute, may be <0)

    const uint32_t sbase = (uint32_t)__cvta_generic_to_shared(sm);
    const long long bbase = (long long)b * S_LEN;

    // depth scale (coefficient threads only need it)
    float ds = 0.0f;
    if (tid < PI * 7) ds = 0.1f * (1.0f + (float)(*layer_idx) * 0.8f);

    // ---- group issue: group g = rows [R0+8g, R0+8g+8) ----
    auto issue_group = [&](int g) {
        const int i0 = phase;              // rows i0, i0+2, i0+4, i0+6
        #pragma unroll
        for (int k = 0; k < 4; ++k) {
            const int i = i0 + 2 * k;
            const int r = R0 + 8 * g + i;  // absolute row in batch
            const bool valid = (r >= 0) && (r < S_LEN);
            const long long rr = valid ? r : 0;
            const float* src = emb + (bbase + rr) * D_DIM + c4 * 4;
            const uint32_t dst = sbase + (((8 * g + i) & (RING - 1)) * D_DIM + c4 * 4) * 4;
            cp_async16(dst, src, valid);
        }
        cp_commit();
    };

    // ---- prologue: fill 3 of 4 ring groups ----
    issue_group(0);
    issue_group(1);
    issue_group(2);

    #pragma unroll 1
    for (int t = 0; t < NIT; ++t) {
        // need groups t, t+1 complete
        if (t < NIT - 1) {
            asm volatile("cp.async.wait_group 1;\n" ::: "memory");
        } else {
            asm volatile("cp.async.wait_group 0;\n" ::: "memory");
        }
        __syncthreads();

        // prefetch group t+3 into group (t-1)'s slots (freed by last iter)
        if (t + 3 <= NIT) issue_group(t + 3);

        const int pos0 = strip0 + PI * t;
        const int u0   = 8 * t;            // ring-unit of row pos0-6

        // ---- norm partials: 13 diffs from 14 rows, split over 2 phases ----
        {
            const int start = phase ? 7 : 0;
            const int nload = phase ? 7 : 8;
            float4 prev = ring4[((u0 + start) & (RING - 1)) * C4 + c4];
            #pragma unroll
            for (int i = 1; i < 8; ++i) {
                if (i < nload) {
                    float4 cur = ring4[((u0 + start + i) & (RING - 1)) * C4 + c4];
                    const float dx = cur.x - prev.x, dy = cur.y - prev.y;
                    const float dz = cur.z - prev.z, dw = cur.w - prev.w;
                    float s = dx * dx + dy * dy + dz * dz + dw * dw;
                    s += __shfl_xor_sync(0xffffffffu, s, 16);
                    s += __shfl_xor_sync(0xffffffffu, s, 8);
                    s += __shfl_xor_sync(0xffffffffu, s, 4);
                    if (lane < 4)
                        sm[SPART_OFF + (start + i - 1) * 16 + wip * 4 + lane] = s;
                    prev = cur;
                }
            }
        }
        __syncthreads();

        // ---- combine 16 partials per diff row -> inverse norm ----
        if (wid < NDIFF) {
            #pragma unroll
            for (int rr8 = 0; rr8 < 2; ++rr8) {
                const int r = wid + 8 * rr8;
                if (r < NDIFF) {
                    float s = (lane < 16) ? sm[SPART_OFF + r * 16 + lane] : 0.0f;
                    s += __shfl_xor_sync(0xffffffffu, s, 8);
                    s += __shfl_xor_sync(0xffffffffu, s, 4);
                    s += __shfl_xor_sync(0xffffffffu, s, 2);
                    s += __shfl_xor_sync(0xffffffffu, s, 1);
                    if (lane == 0) {
                        const float mag = sqrtf(s);
                        sm[SRINV_OFF + r] = (mag > 1e-6f) ? (1.0f / (mag + 1e-8f)) : 0.0f;
                    }
                }
            }
        }
        __syncthreads();

        // ---- telescoped coefficients a[lp][j], j=0..6 ----
        if (tid < PI * 7) {
            const int lp  = tid / 7;
            const int j   = tid % 7;
            const int pos = pos0 + lp;
            float a = 0.0f;
            if (pos >= 1) {
                const int w = (pos < 6) ? pos : 6;
                const float inv = ds / (WSUM[w - 1] + 1e-8f);
                // c(k) = (k<w) ? WT[w-1][k]*inv*srinv[lp+5-k] : 0
                float cj = 0.0f, cjm = 0.0f;
                if (j < w)
                    cj = WT[(w - 1) * 6 + j] * inv * sm[SRINV_OFF + lp + 5 - j];
                if (j >= 1 && (j - 1) < w)
                    cjm = WT[(w - 1) * 6 + (j - 1)] * inv * sm[SRINV_OFF + lp + 6 - j];
                a = cj - cjm;      // j==0: cjm==0
            }
            sm[SCA_OFF + lp * 7 + j] = a;
        }
        __syncthreads();

        // ---- output: each phase emits 4 positions, sliding 7-row window ----
        {
            const int lp0 = phase * 4;
            float4 w7[7];
            #pragma unroll
            for (int i = 0; i < 7; ++i)
                w7[i] = ring4[((u0 + lp0 + i) & (RING - 1)) * C4 + c4];

            float4* op = (float4*)out + (bbase + pos0 + lp0) * C4 + c4;
            #pragma unroll
            for (int q = 0; q < 4; ++q) {
                const int lp = lp0 + q;
                float4 acc = make_float4(0.f, 0.f, 0.f, 0.f);
                #pragma unroll
                for (int j = 0; j < 7; ++j) {
                    const float a = sm[SCA_OFF + lp * 7 + j];
                    const float4 e = w7[6 - j];
                    acc.x = fmaf(a, e.x, acc.x);
                    acc.y = fmaf(a, e.y, acc.y);
                    acc.z = fmaf(a, e.z, acc.z);
                    acc.w = fmaf(a, e.w, acc.w);
                }
                op[q * C4] = acc;
                #pragma unroll
                for (int i = 0; i < 6; ++i) w7[i] = w7[i + 1];
                if (q < 3)
                    w7[6] = ring4[((u0 + lp + 7) & (RING - 1)) * C4 + c4];
            }
        }
        // next iteration's post-wait __syncthreads orders these reads
        // before the ring slots are overwritten.
    }
}

extern "C" void kernel_launch(void* const* d_in, const int* in_sizes, int n_in,
                              void* d_out, int out_size) {
    const float* emb = (const float*)d_in[0];
    const int* layer_idx = (const int*)d_in[1];
    float* out = (float*)d_out;

    const int B = in_sizes[0] / (S_LEN * D_DIM);

    cudaFuncSetAttribute(traj_flow_kernel,
                         cudaFuncAttributeMaxDynamicSharedMemorySize, SMEM_BYTES);

    dim3 grid(S_LEN / STRIP, B);
    traj_flow_kernel<<<grid, 256, SMEM_BYTES>>>(emb, layer_idx, out);
}